// round 10
// baseline (speedup 1.0000x reference)
#include <cuda_runtime.h>
#include <cuda_bf16.h>
#include <cstdint>

#define N_NODES 4096
#define N_FEAT  1024
#define N_HID   8
#define N_HEADS 8
#define N_CLS   16
#define NCOL    64   // N_HEADS * N_HID
#define NGEMMB  256  // 256 row-tiles of 16 rows

// ---------------- scratch (static device globals: allocation-free) ----------
__device__ float g_Wh  [N_NODES * NCOL];
__device__ float g_fs1 [N_NODES * N_HEADS];
__device__ float g_fd1 [N_NODES * N_HEADS];
__device__ float g_Wh2 [N_NODES * N_CLS];
__device__ float g_fs2 [N_NODES];
__device__ float g_fd2 [N_NODES];
__device__ unsigned short g_nbr[(size_t)N_NODES * N_NODES];
__device__ int   g_cnt [N_NODES];

// ---------------- f32x2 packed FMA helpers ----------------------------------
__device__ __forceinline__ void ffma2(unsigned long long& d,
                                      unsigned long long a,
                                      unsigned long long b) {
    asm("fma.rn.f32x2 %0, %1, %2, %0;" : "+l"(d) : "l"(a), "l"(b));
}
__device__ __forceinline__ unsigned long long dup2(float x) {
    unsigned long long r; unsigned xi = __float_as_uint(x);
    asm("mov.b64 %0, {%1, %1};" : "=l"(r) : "r"(xi));
    return r;
}
__device__ __forceinline__ float lo2(unsigned long long v) {
    unsigned a, b; asm("mov.b64 {%0, %1}, %2;" : "=r"(a), "=r"(b) : "l"(v));
    return __uint_as_float(a);
}
__device__ __forceinline__ float hi2(unsigned long long v) {
    unsigned a, b; asm("mov.b64 {%0, %1}, %2;" : "=r"(a), "=r"(b) : "l"(v));
    return __uint_as_float(b);
}

// ---------------- kernel 1: fused full-K GEMM (blocks 0..255) + nbr build ---
// GEMM: BM=16, BN=64 (full), K=1024, 256 threads = 16 rows x 16 colgroups.
// Epilogue computes g_Wh rows AND per-head fs1/fd1 dots (no reduce kernel).
struct GemmS { float Xs[2][32][20]; float Ws[2][32][64]; float sA[128]; };
struct NbrS  { unsigned short sList[4096]; int sWs[9]; };
union SmemU  { GemmS g; NbrS n; };

__global__ __launch_bounds__(256) void fused_kernel(const float* __restrict__ X,
                                                    const float* __restrict__ Wheads,
                                                    const float* __restrict__ adj,
                                                    const float* __restrict__ a_heads) {
    __shared__ SmemU smem;
    const int tid = threadIdx.x;
    const int bid = blockIdx.x;

    if (bid < NGEMMB) {
        // ======== GEMM part
        const int row0 = bid * 16;
        const int tx = tid & 15, ty = tid >> 4;

        if (tid < 64) {
            int h = tid >> 3, f = tid & 7;
            smem.g.sA[tid]      = a_heads[h * 16 + f];
            smem.g.sA[64 + tid] = a_heads[h * 16 + 8 + f];
        }

        float4 xr; float4 wr[2];
        auto ldg_tile = [&](int k0) {
            if (tid < 128) {
                int xrow = tid >> 3, kq = tid & 7;
                xr = *(const float4*)(X + (size_t)(row0 + xrow) * N_FEAT + k0 + kq * 4);
            }
#pragma unroll
            for (int i = 0; i < 2; i++) {
                int f = tid + i * 256;
                int kr = f >> 4, c4 = (f & 15) * 4;
                wr[i] = *(const float4*)(Wheads + ((c4 >> 3) << 13) + ((k0 + kr) << 3) + (c4 & 7));
            }
        };
        auto sts_tile = [&](int b) {
            if (tid < 128) {
                int xrow = tid >> 3, kq = tid & 7;
                smem.g.Xs[b][kq * 4 + 0][xrow] = xr.x;
                smem.g.Xs[b][kq * 4 + 1][xrow] = xr.y;
                smem.g.Xs[b][kq * 4 + 2][xrow] = xr.z;
                smem.g.Xs[b][kq * 4 + 3][xrow] = xr.w;
            }
#pragma unroll
            for (int i = 0; i < 2; i++) {
                int f = tid + i * 256;
                int kr = f >> 4, c4 = (f & 15) * 4;
                *(float4*)&smem.g.Ws[b][kr][c4] = wr[i];
            }
        };

        unsigned long long acc0 = 0ull, acc1 = 0ull;

        ldg_tile(0);
        sts_tile(0);
        __syncthreads();

#pragma unroll 1
        for (int t = 0; t < 32; t++) {
            int cur = t & 1;
            if (t < 31) ldg_tile((t + 1) * 32);
#pragma unroll
            for (int k = 0; k < 32; k++) {
                float xs = smem.g.Xs[cur][k][ty];
                ulonglong2 wv = *(const ulonglong2*)&smem.g.Ws[cur][k][tx * 4];
                unsigned long long xv = dup2(xs);
                ffma2(acc0, xv, wv.x); ffma2(acc1, xv, wv.y);
            }
            if (t < 31) {
                __syncthreads();
                sts_tile(cur ^ 1);
                __syncthreads();
            }
        }

        float o0 = lo2(acc0), o1 = hi2(acc0), o2 = lo2(acc1), o3 = hi2(acc1);
        int row = row0 + ty;
        *(float4*)(g_Wh + (size_t)row * NCOL + tx * 4) = make_float4(o0, o1, o2, o3);
        float fsp = o0 * smem.g.sA[tx * 4] + o1 * smem.g.sA[tx * 4 + 1]
                  + o2 * smem.g.sA[tx * 4 + 2] + o3 * smem.g.sA[tx * 4 + 3];
        float fdp = o0 * smem.g.sA[64 + tx * 4] + o1 * smem.g.sA[64 + tx * 4 + 1]
                  + o2 * smem.g.sA[64 + tx * 4 + 2] + o3 * smem.g.sA[64 + tx * 4 + 3];
        fsp += __shfl_xor_sync(0xffffffffu, fsp, 1);
        fdp += __shfl_xor_sync(0xffffffffu, fdp, 1);
        if ((tx & 1) == 0) {
            int h = tx >> 1;
            g_fs1[row * N_HEADS + h] = fsp;
            g_fd1[row * N_HEADS + h] = fdp;
        }
    } else {
        // ======== nbr part: one block per row, 16 adj elems per thread
        int row = bid - NGEMMB;
        const float* arow = adj + (size_t)row * N_NODES;
        int base = tid * 16;
        unsigned mask = 0;
#pragma unroll
        for (int q = 0; q < 4; q++) {
            float4 v = *(const float4*)(arow + base + q * 4);
            if (v.x > 0.f) mask |= 1u << (q * 4 + 0);
            if (v.y > 0.f) mask |= 1u << (q * 4 + 1);
            if (v.z > 0.f) mask |= 1u << (q * 4 + 2);
            if (v.w > 0.f) mask |= 1u << (q * 4 + 3);
        }
        int c = __popc(mask);
        int lane = tid & 31, wid = tid >> 5;
        int v = c;
#pragma unroll
        for (int off = 1; off < 32; off <<= 1) {
            int n = __shfl_up_sync(0xffffffffu, v, off);
            if (lane >= off) v += n;
        }
        if (lane == 31) smem.n.sWs[wid] = v;
        __syncthreads();
        if (tid == 0) {
            int a = 0;
#pragma unroll
            for (int w = 0; w < 8; w++) { int t = smem.n.sWs[w]; smem.n.sWs[w] = a; a += t; }
            smem.n.sWs[8] = a;
        }
        __syncthreads();
        int pos = smem.n.sWs[wid] + v - c;
        unsigned m = mask;
        while (m) {
            int b = __ffs(m) - 1;
            m &= m - 1;
            smem.n.sList[pos++] = (unsigned short)(base + b);
        }
        __syncthreads();
        int cnt = smem.n.sWs[8];
        if (tid == 0) g_cnt[row] = cnt;
        for (int t = tid; t < cnt; t += 256)
            g_nbr[(size_t)row * N_NODES + t] = smem.n.sList[t];
    }
}

// ---------------- kernel 2: layer-1 gather attention + elu + W2 + dots ------
// 256 threads = 16 edge-slots x 16 lanes, float4 gathers.
// Fixed-size (128) list staging: no dependency on the cnt load.
__global__ __launch_bounds__(256) void attnA_kernel(const float* __restrict__ Wf,
                                                    const float* __restrict__ af) {
    __shared__ unsigned short sList[128];
    __shared__ float sfs[8];
    __shared__ float sH[64];
    __shared__ float sWf[64 * 16];
    __shared__ float sAf[32];
    __shared__ float sAcc[16][64];
    __shared__ float sS[16][8];
    __shared__ float sPart[8][16];

    int row = blockIdx.x, tid = threadIdx.x;
    int cnt = g_cnt[row];                            // in flight with staging
    const unsigned short* nbg = g_nbr + (size_t)row * N_NODES;
    if (tid < 128) sList[tid] = nbg[tid];            // fixed-size stage
    if (tid < 8) sfs[tid] = g_fs1[row * N_HEADS + tid];
    for (int t = tid; t < 1024; t += 256) sWf[t] = Wf[t];
    if (tid < 32) sAf[tid] = af[tid];
    __syncthreads();

    // phase 1: gather attention, 16 edge-slots x 16 lanes, float4 per lane
    {
        int slot = tid >> 4, q = tid & 15;
        int h = q >> 1;
        float fsa = sfs[h];
        float4 acc = make_float4(0.f, 0.f, 0.f, 0.f);
        float ssum = 0.f;
        for (int e = slot; e < cnt; e += 16) {
            int j = e < 128 ? sList[e] : nbg[e];
            float fd = __ldg(&g_fd1[j * N_HEADS + h]);
            float4 wv = __ldg((const float4*)&g_Wh[(size_t)j * NCOL + q * 4]);
            float ev = fsa + fd;
            ev = ev > 0.f ? ev : 0.2f * ev;
            float w = __expf(ev);
            acc.x += w * wv.x; acc.y += w * wv.y;
            acc.z += w * wv.z; acc.w += w * wv.w;
            if ((q & 1) == 0) ssum += w;
        }
        *(float4*)&sAcc[slot][q * 4] = acc;
        if ((q & 1) == 0) sS[slot][h] = ssum;
    }
    __syncthreads();
    if (tid < 64) {
        int l = tid, h = l >> 3;
        float a = 0.f, S = 0.f;
#pragma unroll
        for (int s = 0; s < 16; s++) { a += sAcc[s][l]; S += sS[s][h]; }
        float h1 = a / S;
        sH[l] = h1 > 0.f ? h1 : __expf(h1) - 1.f;   // elu fused
    }
    __syncthreads();

    // phase 2: 64x16 projection + feature dots
    if (tid < 128) {
        int kg = tid >> 4, cc = tid & 15;
        float p = 0.f;
#pragma unroll
        for (int q = 0; q < 8; q++) {
            int kk = kg * 8 + q;
            p += sH[kk] * sWf[kk * 16 + cc];
        }
        sPart[kg][cc] = p;
    }
    __syncthreads();
    if (tid < 16) {
        float acc2 = 0.f;
#pragma unroll
        for (int q = 0; q < 8; q++) acc2 += sPart[q][tid];
        g_Wh2[row * N_CLS + tid] = acc2;
        float fsp = acc2 * sAf[tid], fdp = acc2 * sAf[16 + tid];
#pragma unroll
        for (int off = 1; off < 16; off <<= 1) {
            fsp += __shfl_xor_sync(0x0000ffffu, fsp, off);
            fdp += __shfl_xor_sync(0x0000ffffu, fdp, off);
        }
        if (tid == 0) { g_fs2[row] = fsp; g_fd2[row] = fdp; }
    }
}

// ---------------- kernel 3: layer-2 attention + log_softmax -----------------
// 4 rows/block (1024 blocks); per row 64 threads = 16 edge-slots x 4 lanes.
// Fixed-size (128/row) staging, no cnt dependency.
__global__ __launch_bounds__(256) void attn2_kernel(float* __restrict__ out) {
    __shared__ unsigned short sNb[4][128];
    __shared__ int sCnt[4];
    __shared__ float sFs[4];
    __shared__ float rAcc[4][16][16];
    __shared__ float rS[4][16];

    int tid = threadIdx.x;
    int row0 = blockIdx.x * 4;
    if (tid < 4) {
        sCnt[tid] = g_cnt[row0 + tid];
        sFs[tid] = g_fs2[row0 + tid];
    }
#pragma unroll
    for (int t = tid; t < 512; t += 256) {
        int r = t >> 7, idx = t & 127;
        sNb[r][idx] = g_nbr[(size_t)(row0 + r) * N_NODES + idx];
    }
    __syncthreads();

    int rl = tid >> 6;
    int t64 = tid & 63;
    int slot = t64 >> 2, q = t64 & 3;
    int row = row0 + rl;
    int cnt = sCnt[rl];
    float fs = sFs[rl];
    const unsigned short* nbg = g_nbr + (size_t)row * N_NODES;
    float4 acc = make_float4(0.f, 0.f, 0.f, 0.f);
    float s = 0.f;
    for (int e = slot; e < cnt; e += 16) {
        int j = e < 128 ? sNb[rl][e] : nbg[e];
        float fd = __ldg(&g_fd2[j]);
        float4 p = __ldg((const float4*)&g_Wh2[j * N_CLS + q * 4]);
        float ev = fs + fd;
        ev = ev > 0.f ? ev : 0.2f * ev;
        float w = __expf(ev);
        acc.x += w * p.x; acc.y += w * p.y;
        acc.z += w * p.z; acc.w += w * p.w;
        if (q == 0) s += w;
    }
    *(float4*)&rAcc[rl][slot][q * 4] = acc;
    if (q == 0) rS[rl][slot] = s;
    __syncthreads();

    if (tid < 64) {
        int rr = tid >> 4, c2 = tid & 15;
        float a = 0.f, S = 0.f;
#pragma unroll
        for (int sl = 0; sl < 16; sl++) { a += rAcc[rr][sl][c2]; S += rS[rr][sl]; }
        float o = a / S;
        float mx = o;
#pragma unroll
        for (int off = 8; off; off >>= 1)
            mx = fmaxf(mx, __shfl_xor_sync(0xffffffffu, mx, off, 16));
        float ex = __expf(o - mx), sum = ex;
#pragma unroll
        for (int off = 8; off; off >>= 1)
            sum += __shfl_xor_sync(0xffffffffu, sum, off, 16);
        out[(row0 + rr) * N_CLS + c2] = o - mx - __logf(sum);
    }
}

// ---------------- launch ----------------------------------------------------
extern "C" void kernel_launch(void* const* d_in, const int* in_sizes, int n_in,
                              void* d_out, int out_size) {
    (void)in_sizes; (void)n_in; (void)out_size;
    const float* x       = (const float*)d_in[0];
    const float* adj     = (const float*)d_in[1];
    const float* W_heads = (const float*)d_in[2];
    const float* a_heads = (const float*)d_in[3];
    const float* W_final = (const float*)d_in[4];
    const float* a_final = (const float*)d_in[5];
    float* out = (float*)d_out;

    fused_kernel<<<NGEMMB + N_NODES, 256>>>(x, W_heads, adj, a_heads);
    attnA_kernel<<<N_NODES, 256>>>(W_final, a_final);
    attn2_kernel<<<1024, 256>>>(out);
}

// round 13
// speedup vs baseline: 1.9905x; 1.9905x over previous
#include <cuda_runtime.h>
#include <cuda_bf16.h>
#include <cstdint>

#define N_NODES 4096
#define N_FEAT  1024
#define N_HID   8
#define N_HEADS 8
#define N_CLS   16
#define NCOL    64   // N_HEADS * N_HID
#define KSPLIT  8
#define NGEMMB  512  // 64 row-tiles x 8 k-splits

// ---------------- scratch (static device globals: allocation-free) ----------
__device__ float g_part[KSPLIT][N_NODES * NCOL];
__device__ float g_Wh  [N_NODES * NCOL];
__device__ float g_fs1 [N_NODES * N_HEADS];
__device__ float g_fd1 [N_NODES * N_HEADS];
__device__ float g_Wh2 [N_NODES * N_CLS];
__device__ float g_fs2 [N_NODES];
__device__ float g_fd2 [N_NODES];
__device__ unsigned short g_nbr[(size_t)N_NODES * N_NODES];
__device__ int   g_cnt [N_NODES];

// ---------------- f32x2 packed FMA helpers ----------------------------------
__device__ __forceinline__ void ffma2(unsigned long long& d,
                                      unsigned long long a,
                                      unsigned long long b) {
    asm("fma.rn.f32x2 %0, %1, %2, %0;" : "+l"(d) : "l"(a), "l"(b));
}
__device__ __forceinline__ unsigned long long dup2(float x) {
    unsigned long long r; unsigned xi = __float_as_uint(x);
    asm("mov.b64 %0, {%1, %1};" : "=l"(r) : "r"(xi));
    return r;
}
__device__ __forceinline__ float lo2(unsigned long long v) {
    unsigned a, b; asm("mov.b64 {%0, %1}, %2;" : "=r"(a), "=r"(b) : "l"(v));
    return __uint_as_float(a);
}
__device__ __forceinline__ float hi2(unsigned long long v) {
    unsigned a, b; asm("mov.b64 {%0, %1}, %2;" : "=r"(a), "=r"(b) : "l"(v));
    return __uint_as_float(b);
}

// ---------------- kernel 1: fused GEMM1 (blocks 0..511) + nbr build ---------
struct GemmS { float Xs[2][32][72]; float Ws[2][32][64]; };
struct NbrS  { unsigned short sList[4096]; int sWs[9]; };
union SmemU  { GemmS g; NbrS n; };

__global__ __launch_bounds__(256) void fused_kernel(const float* __restrict__ X,
                                                    const float* __restrict__ Wheads,
                                                    const float* __restrict__ adj) {
    __shared__ SmemU smem;
    const int tid = threadIdx.x;
    const int bid = blockIdx.x;

    if (bid < NGEMMB) {
        // ======== GEMM part: BM=64, BN=64, BK=32; thread tile 4 rows x 4 cols
        const int rt = bid & 63, ks = bid >> 6;
        const int row0 = rt * 64, kbase = ks * 128;
        const int tx = tid & 15, ty = tid >> 4;

        float4 xr[2], wr[2];
        auto ldg_tile = [&](int k0) {
#pragma unroll
            for (int i = 0; i < 2; i++) {
                int f = tid + i * 256;
                int xrow = f >> 3, kq = f & 7;
                xr[i] = *(const float4*)(X + (size_t)(row0 + xrow) * N_FEAT + k0 + kq * 4);
                int kr = f >> 4, c4 = (f & 15) * 4;
                wr[i] = *(const float4*)(Wheads + ((c4 >> 3) << 13) + ((k0 + kr) << 3) + (c4 & 7));
            }
        };
        auto sts_tile = [&](int b) {
#pragma unroll
            for (int i = 0; i < 2; i++) {
                int f = tid + i * 256;
                int xrow = f >> 3, kq = f & 7;
                smem.g.Xs[b][kq * 4 + 0][xrow] = xr[i].x;
                smem.g.Xs[b][kq * 4 + 1][xrow] = xr[i].y;
                smem.g.Xs[b][kq * 4 + 2][xrow] = xr[i].z;
                smem.g.Xs[b][kq * 4 + 3][xrow] = xr[i].w;
                int kr = f >> 4, c4 = (f & 15) * 4;
                *(float4*)&smem.g.Ws[b][kr][c4] = wr[i];
            }
        };

        unsigned long long acc[4][2];
#pragma unroll
        for (int r = 0; r < 4; r++) { acc[r][0] = 0ull; acc[r][1] = 0ull; }

        ldg_tile(kbase);
        sts_tile(0);
        __syncthreads();

#pragma unroll 1
        for (int t = 0; t < 4; t++) {
            int cur = t & 1;
            if (t < 3) ldg_tile(kbase + (t + 1) * 32);
#pragma unroll
            for (int k = 0; k < 32; k++) {
                float4 xv4 = *(const float4*)&smem.g.Xs[cur][k][ty * 4];
                ulonglong2 wv = *(const ulonglong2*)&smem.g.Ws[cur][k][tx * 4];
                unsigned long long xv;
                xv = dup2(xv4.x); ffma2(acc[0][0], xv, wv.x); ffma2(acc[0][1], xv, wv.y);
                xv = dup2(xv4.y); ffma2(acc[1][0], xv, wv.x); ffma2(acc[1][1], xv, wv.y);
                xv = dup2(xv4.z); ffma2(acc[2][0], xv, wv.x); ffma2(acc[2][1], xv, wv.y);
                xv = dup2(xv4.w); ffma2(acc[3][0], xv, wv.x); ffma2(acc[3][1], xv, wv.y);
            }
            if (t < 3) {
                __syncthreads();
                sts_tile(cur ^ 1);
                __syncthreads();
            }
        }

        float* dst = g_part[ks];
#pragma unroll
        for (int r = 0; r < 4; r++) {
            int row = row0 + ty * 4 + r;
            *(float4*)(dst + (size_t)row * NCOL + tx * 4) =
                make_float4(lo2(acc[r][0]), hi2(acc[r][0]), lo2(acc[r][1]), hi2(acc[r][1]));
        }
    } else {
        // ======== nbr part: one block per row, 16 adj elems per thread
        int row = bid - NGEMMB;
        const float* arow = adj + (size_t)row * N_NODES;
        int base = tid * 16;
        unsigned mask = 0;
#pragma unroll
        for (int q = 0; q < 4; q++) {
            float4 v = *(const float4*)(arow + base + q * 4);
            if (v.x > 0.f) mask |= 1u << (q * 4 + 0);
            if (v.y > 0.f) mask |= 1u << (q * 4 + 1);
            if (v.z > 0.f) mask |= 1u << (q * 4 + 2);
            if (v.w > 0.f) mask |= 1u << (q * 4 + 3);
        }
        int c = __popc(mask);
        int lane = tid & 31, wid = tid >> 5;
        int v = c;
#pragma unroll
        for (int off = 1; off < 32; off <<= 1) {
            int n = __shfl_up_sync(0xffffffffu, v, off);
            if (lane >= off) v += n;
        }
        if (lane == 31) smem.n.sWs[wid] = v;
        __syncthreads();
        if (tid == 0) {
            int a = 0;
#pragma unroll
            for (int w = 0; w < 8; w++) { int t = smem.n.sWs[w]; smem.n.sWs[w] = a; a += t; }
            smem.n.sWs[8] = a;
        }
        __syncthreads();
        int pos = smem.n.sWs[wid] + v - c;
        unsigned m = mask;
        while (m) {
            int b = __ffs(m) - 1;
            m &= m - 1;
            smem.n.sList[pos++] = (unsigned short)(base + b);
        }
        __syncthreads();
        int cnt = smem.n.sWs[8];
        if (tid == 0) g_cnt[row] = cnt;
        for (int t = tid; t < cnt; t += 256)
            g_nbr[(size_t)row * N_NODES + t] = smem.n.sList[t];
    }
}

// ---------------- kernel 2: split-K reduce + per-head feature dots -----------
__global__ __launch_bounds__(256) void reduce_kernel(const float* __restrict__ a_heads) {
    __shared__ float sAsrc[64], sAdst[64];
    int tid = threadIdx.x;
    if (tid < 64) {
        int h = tid >> 3, f = tid & 7;
        sAsrc[tid] = a_heads[h * 16 + f];
        sAdst[tid] = a_heads[h * 16 + 8 + f];
    }
    __syncthreads();
    int idx = blockIdx.x * 256 + tid;
    int c = idx & 63;
    float s = 0.f;
#pragma unroll
    for (int q = 0; q < KSPLIT; q++) s += g_part[q][idx];
    g_Wh[idx] = s;
    float fsp = s * sAsrc[c], fdp = s * sAdst[c];
#pragma unroll
    for (int off = 1; off < 8; off <<= 1) {
        fsp += __shfl_xor_sync(0xffffffffu, fsp, off);
        fdp += __shfl_xor_sync(0xffffffffu, fdp, off);
    }
    if ((c & 7) == 0) {
        int row = idx >> 6, h = c >> 3;
        g_fs1[row * N_HEADS + h] = fsp;
        g_fd1[row * N_HEADS + h] = fdp;
    }
}

// ---------------- kernel 3: layer-1 gather attention + elu + W2 + dots ------
// 256 threads = 16 edge-slots x 16 lanes, float4 gathers.
// Fixed-size (128) list staging: no dependency on the cnt load.
__global__ __launch_bounds__(256) void attnA_kernel(const float* __restrict__ Wf,
                                                    const float* __restrict__ af) {
    __shared__ unsigned short sList[128];
    __shared__ float sfs[8];
    __shared__ float sH[64];
    __shared__ float sWf[64 * 16];
    __shared__ float sAf[32];
    __shared__ float sAcc[16][64];
    __shared__ float sS[16][8];
    __shared__ float sPart[8][16];

    int row = blockIdx.x, tid = threadIdx.x;
    int cnt = g_cnt[row];                            // in flight with staging
    const unsigned short* nbg = g_nbr + (size_t)row * N_NODES;
    if (tid < 128) sList[tid] = nbg[tid];            // fixed-size stage
    if (tid < 8) sfs[tid] = g_fs1[row * N_HEADS + tid];
    for (int t = tid; t < 1024; t += 256) sWf[t] = Wf[t];
    if (tid < 32) sAf[tid] = af[tid];
    __syncthreads();

    // phase 1: gather attention, 16 edge-slots x 16 lanes, float4 per lane
    {
        int slot = tid >> 4, q = tid & 15;
        int h = q >> 1;
        float fsa = sfs[h];
        float4 acc = make_float4(0.f, 0.f, 0.f, 0.f);
        float ssum = 0.f;
        for (int e = slot; e < cnt; e += 16) {
            int j = e < 128 ? sList[e] : nbg[e];
            float fd = __ldg(&g_fd1[j * N_HEADS + h]);
            float4 wv = __ldg((const float4*)&g_Wh[(size_t)j * NCOL + q * 4]);
            float ev = fsa + fd;
            ev = ev > 0.f ? ev : 0.2f * ev;
            float w = __expf(ev);
            acc.x += w * wv.x; acc.y += w * wv.y;
            acc.z += w * wv.z; acc.w += w * wv.w;
            if ((q & 1) == 0) ssum += w;
        }
        *(float4*)&sAcc[slot][q * 4] = acc;
        if ((q & 1) == 0) sS[slot][h] = ssum;
    }
    __syncthreads();
    if (tid < 64) {
        int l = tid, h = l >> 3;
        float a = 0.f, S = 0.f;
#pragma unroll
        for (int s = 0; s < 16; s++) { a += sAcc[s][l]; S += sS[s][h]; }
        float h1 = a / S;
        sH[l] = h1 > 0.f ? h1 : __expf(h1) - 1.f;   // elu fused
    }
    __syncthreads();

    // phase 2: 64x16 projection + feature dots
    if (tid < 128) {
        int kg = tid >> 4, cc = tid & 15;
        float p = 0.f;
#pragma unroll
        for (int q = 0; q < 8; q++) {
            int kk = kg * 8 + q;
            p += sH[kk] * sWf[kk * 16 + cc];
        }
        sPart[kg][cc] = p;
    }
    __syncthreads();
    if (tid < 16) {
        float acc2 = 0.f;
#pragma unroll
        for (int q = 0; q < 8; q++) acc2 += sPart[q][tid];
        g_Wh2[row * N_CLS + tid] = acc2;
        float fsp = acc2 * sAf[tid], fdp = acc2 * sAf[16 + tid];
#pragma unroll
        for (int off = 1; off < 16; off <<= 1) {
            fsp += __shfl_xor_sync(0x0000ffffu, fsp, off);
            fdp += __shfl_xor_sync(0x0000ffffu, fdp, off);
        }
        if (tid == 0) { g_fs2[row] = fsp; g_fd2[row] = fdp; }
    }
}

// ---------------- kernel 4: layer-2 attention + log_softmax -----------------
// 4 rows/block (1024 blocks); per row 64 threads = 16 edge-slots x 4 lanes.
// Fixed-size (128/row) staging, no cnt dependency.
__global__ __launch_bounds__(256) void attn2_kernel(float* __restrict__ out) {
    __shared__ unsigned short sNb[4][128];
    __shared__ int sCnt[4];
    __shared__ float sFs[4];
    __shared__ float rAcc[4][16][16];
    __shared__ float rS[4][16];

    int tid = threadIdx.x;
    int row0 = blockIdx.x * 4;
    if (tid < 4) {
        sCnt[tid] = g_cnt[row0 + tid];
        sFs[tid] = g_fs2[row0 + tid];
    }
#pragma unroll
    for (int t = tid; t < 512; t += 256) {
        int r = t >> 7, idx = t & 127;
        sNb[r][idx] = g_nbr[(size_t)(row0 + r) * N_NODES + idx];
    }
    __syncthreads();

    int rl = tid >> 6;
    int t64 = tid & 63;
    int slot = t64 >> 2, q = t64 & 3;
    int row = row0 + rl;
    int cnt = sCnt[rl];
    float fs = sFs[rl];
    const unsigned short* nbg = g_nbr + (size_t)row * N_NODES;
    float4 acc = make_float4(0.f, 0.f, 0.f, 0.f);
    float s = 0.f;
    for (int e = slot; e < cnt; e += 16) {
        int j = e < 128 ? sNb[rl][e] : nbg[e];
        float fd = __ldg(&g_fd2[j]);
        float4 p = __ldg((const float4*)&g_Wh2[j * N_CLS + q * 4]);
        float ev = fs + fd;
        ev = ev > 0.f ? ev : 0.2f * ev;
        float w = __expf(ev);
        acc.x += w * p.x; acc.y += w * p.y;
        acc.z += w * p.z; acc.w += w * p.w;
        if (q == 0) s += w;
    }
    *(float4*)&rAcc[rl][slot][q * 4] = acc;
    if (q == 0) rS[rl][slot] = s;
    __syncthreads();

    if (tid < 64) {
        int rr = tid >> 4, c2 = tid & 15;
        float a = 0.f, S = 0.f;
#pragma unroll
        for (int sl = 0; sl < 16; sl++) { a += rAcc[rr][sl][c2]; S += rS[rr][sl]; }
        float o = a / S;
        float mx = o;
#pragma unroll
        for (int off = 8; off; off >>= 1)
            mx = fmaxf(mx, __shfl_xor_sync(0xffffffffu, mx, off, 16));
        float ex = __expf(o - mx), sum = ex;
#pragma unroll
        for (int off = 8; off; off >>= 1)
            sum += __shfl_xor_sync(0xffffffffu, sum, off, 16);
        out[(row0 + rr) * N_CLS + c2] = o - mx - __logf(sum);
    }
}

// ---------------- launch ----------------------------------------------------
extern "C" void kernel_launch(void* const* d_in, const int* in_sizes, int n_in,
                              void* d_out, int out_size) {
    (void)in_sizes; (void)n_in; (void)out_size;
    const float* x       = (const float*)d_in[0];
    const float* adj     = (const float*)d_in[1];
    const float* W_heads = (const float*)d_in[2];
    const float* a_heads = (const float*)d_in[3];
    const float* W_final = (const float*)d_in[4];
    const float* a_final = (const float*)d_in[5];
    float* out = (float*)d_out;

    fused_kernel<<<NGEMMB + N_NODES, 256>>>(x, W_heads, adj);
    reduce_kernel<<<1024, 256>>>(a_heads);
    attnA_kernel<<<N_NODES, 256>>>(W_final, a_final);
    attn2_kernel<<<1024, 256>>>(out);
}